// round 1
// baseline (speedup 1.0000x reference)
#include <cuda_runtime.h>
#include <cstdint>

// Shapes are fixed by the problem: value [8,4096,1024], last [8,1024],
// W [1024,1024], bias [1024]. Output [8,1,1024] float32.
#define BB 8
#define TT 4096
#define HH 1024
#define TCH 16          // T-chunks for context partial reduction
#define TSEG (TT/TCH)   // 256 timesteps per context block

// -------- scratch (__device__ globals; no allocation allowed) --------
__device__ float g_q[BB * HH];            // q[b] = W^T last[b]
__device__ float g_score[BB * TT];        // raw scores
__device__ float g_attn[BB * TT];         // softmax(scores)
__device__ float g_partial[TCH * BB * HH];// split-T context partials

// ---------------------------------------------------------------------
// Kernel 1: q[b,h] = sum_o W[o,h] * last[b,o]
// grid (HH/256, BB), block 256. W read column-coalesced; W (4MB) L2-resident
// across the 8 batches.
// ---------------------------------------------------------------------
__global__ void k_query(const float* __restrict__ W,
                        const float* __restrict__ last) {
    __shared__ float ls[HH];
    const int b = blockIdx.y;
    for (int i = threadIdx.x; i < HH; i += blockDim.x)
        ls[i] = last[b * HH + i];
    __syncthreads();

    const int h = blockIdx.x * blockDim.x + threadIdx.x;
    float acc = 0.f;
    #pragma unroll 8
    for (int o = 0; o < HH; o++)
        acc = fmaf(W[o * HH + h], ls[o], acc);
    g_q[b * HH + h] = acc;
}

// ---------------------------------------------------------------------
// Kernel 2: score[b,t] = value[b,t,:] . q[b,:]
// One warp per t, float4 loads (8 per lane). Block = 8 warps sharing one
// smem copy of q[b]. grid = B*T/8 = 4096 blocks. Streams 128 MB.
// ---------------------------------------------------------------------
__global__ void k_score(const float* __restrict__ value) {
    __shared__ float qs[HH];
    const int tpb = TT / 8;                 // t-groups per batch
    const int b  = blockIdx.x / tpb;
    const int t0 = (blockIdx.x % tpb) * 8;

    for (int i = threadIdx.x; i < HH; i += blockDim.x)
        qs[i] = g_q[b * HH + i];
    __syncthreads();

    const int w    = threadIdx.x >> 5;
    const int lane = threadIdx.x & 31;
    const int t    = t0 + w;

    const float4* __restrict__ v =
        reinterpret_cast<const float4*>(value + ((size_t)b * TT + t) * HH);
    const float4* __restrict__ q4 = reinterpret_cast<const float4*>(qs);

    float acc = 0.f;
    #pragma unroll
    for (int i = 0; i < HH / 128; i++) {      // 8 float4 per lane
        float4 x = v[i * 32 + lane];
        float4 q = q4[i * 32 + lane];
        acc = fmaf(x.x, q.x, acc);
        acc = fmaf(x.y, q.y, acc);
        acc = fmaf(x.z, q.z, acc);
        acc = fmaf(x.w, q.w, acc);
    }
    #pragma unroll
    for (int off = 16; off; off >>= 1)
        acc += __shfl_xor_sync(0xFFFFFFFFu, acc, off);
    if (lane == 0)
        g_score[b * TT + t] = acc;
}

// ---------------------------------------------------------------------
// Kernel 3: softmax over T per batch. grid = B blocks, 256 threads,
// 16 elements/thread held in registers.
// ---------------------------------------------------------------------
__global__ void k_softmax() {
    const int b = blockIdx.x;
    const int tid = threadIdx.x;
    __shared__ float red[32];

    float v[TT / 256];
    float mx = -1e30f;
    #pragma unroll
    for (int i = 0; i < TT / 256; i++) {
        v[i] = g_score[b * TT + tid + i * 256];
        mx = fmaxf(mx, v[i]);
    }
    // block max
    #pragma unroll
    for (int off = 16; off; off >>= 1)
        mx = fmaxf(mx, __shfl_xor_sync(0xFFFFFFFFu, mx, off));
    if ((tid & 31) == 0) red[tid >> 5] = mx;
    __syncthreads();
    if (tid < 32) {
        float m = (tid < 8) ? red[tid] : -1e30f;
        #pragma unroll
        for (int off = 4; off; off >>= 1)
            m = fmaxf(m, __shfl_xor_sync(0xFFFFFFFFu, m, off));
        if (tid == 0) red[0] = m;
    }
    __syncthreads();
    mx = red[0];

    float s = 0.f;
    #pragma unroll
    for (int i = 0; i < TT / 256; i++) {
        v[i] = __expf(v[i] - mx);
        s += v[i];
    }
    __syncthreads();
    #pragma unroll
    for (int off = 16; off; off >>= 1)
        s += __shfl_xor_sync(0xFFFFFFFFu, s, off);
    if ((tid & 31) == 0) red[tid >> 5] = s;
    __syncthreads();
    if (tid < 32) {
        float m = (tid < 8) ? red[tid] : 0.f;
        #pragma unroll
        for (int off = 4; off; off >>= 1)
            m += __shfl_xor_sync(0xFFFFFFFFu, m, off);
        if (tid == 0) red[0] = m;
    }
    __syncthreads();
    const float inv = 1.0f / red[0];

    #pragma unroll
    for (int i = 0; i < TT / 256; i++)
        g_attn[b * TT + tid + i * 256] = v[i] * inv;
}

// ---------------------------------------------------------------------
// Kernel 4: context partials. grid (HH/256, TCH, BB), block 256.
// Thread <-> h one-to-one within a 256-wide h chunk; loops over TSEG
// timesteps. Each t-row read is 1 KB contiguous per block. Streams 128 MB.
// ---------------------------------------------------------------------
__global__ void k_context(const float* __restrict__ value) {
    const int b  = blockIdx.z;
    const int h  = blockIdx.x * blockDim.x + threadIdx.x;
    const int t0 = blockIdx.y * TSEG;

    __shared__ float as[TSEG];
    for (int i = threadIdx.x; i < TSEG; i += blockDim.x)
        as[i] = g_attn[b * TT + t0 + i];
    __syncthreads();

    const float* __restrict__ vp = value + ((size_t)b * TT + t0) * HH + h;
    float acc = 0.f;
    #pragma unroll 8
    for (int i = 0; i < TSEG; i++)
        acc = fmaf(as[i], vp[(size_t)i * HH], acc);

    g_partial[(blockIdx.y * BB + b) * HH + h] = acc;
}

// ---------------------------------------------------------------------
// Kernel 5: deterministic reduce of the TCH partials -> out [B,1,H]
// ---------------------------------------------------------------------
__global__ void k_reduce(float* __restrict__ out) {
    const int idx = blockIdx.x * blockDim.x + threadIdx.x; // b*HH + h
    float s = 0.f;
    #pragma unroll
    for (int c = 0; c < TCH; c++)
        s += g_partial[c * BB * HH + idx];
    out[idx] = s;
}

// ---------------------------------------------------------------------
extern "C" void kernel_launch(void* const* d_in, const int* in_sizes, int n_in,
                              void* d_out, int out_size) {
    const float* value = (const float*)d_in[0];  // [B,T,H]
    const float* last  = (const float*)d_in[1];  // [B,H]
    const float* W     = (const float*)d_in[2];  // [H,H]
    // d_in[3] = bias: constant shift per batch, cancels in softmax. Unused.
    float* out = (float*)d_out;                  // [B,1,H]
    (void)in_sizes; (void)n_in; (void)out_size;

    dim3 g1(HH / 256, BB);
    k_query<<<g1, 256>>>(W, last);

    k_score<<<BB * (TT / 8), 256>>>(value);

    k_softmax<<<BB, 256>>>();

    dim3 g4(HH / 256, TCH, BB);
    k_context<<<g4, 256>>>(value);

    k_reduce<<<(BB * HH) / 256, 256>>>(out);
}

// round 2
// speedup vs baseline: 2.5098x; 2.5098x over previous
#include <cuda_runtime.h>
#include <cstdint>

// Shapes fixed: value [8,4096,1024], last [8,1024], W [1024,1024], b [1024].
#define BB 8
#define TT 4096
#define HH 1024

#define RANGES 16              // T-splits per batch (fused kernel grid.x)
#define TR (TT / RANGES)       // 256 timesteps per block
#define NW 16                  // warps per fused block (512 threads)
#define RPW 2                  // rows per warp per iteration
#define NITER (TR / (NW * RPW))// 8 iterations

#define OCH 16                 // o-splits for query partials
#define OSEG (HH / OCH)        // 64

// -------- scratch (__device__ globals; no allocation allowed) --------
__device__ __align__(16) float g_q[BB * HH];
__device__ __align__(16) float g_qpart[OCH * BB * HH];
__device__ __align__(16) float g_cpart[BB * RANGES * HH];
__device__ float g_mpart[BB * RANGES];
__device__ float g_spart[BB * RANGES];

// ---------------------------------------------------------------------
// Kernel 1: query partials. q[b,h] = sum_o W[o,h]*last[b,o].
// Each block covers 256 h-cols x 64 o-rows, computing ALL 8 batches per
// W element load (W streamed once). grid (HH/256, OCH) = 64 blocks.
// ---------------------------------------------------------------------
__global__ void k_query_part(const float* __restrict__ W,
                             const float* __restrict__ last) {
    __shared__ float ls[BB * OSEG];
    const int oc = blockIdx.y;
    const int h  = blockIdx.x * 256 + threadIdx.x;

    for (int i = threadIdx.x; i < BB * OSEG; i += 256) {
        int b = i / OSEG, o = i % OSEG;
        ls[i] = last[b * HH + oc * OSEG + o];
    }
    __syncthreads();

    float acc[BB];
#pragma unroll
    for (int b = 0; b < BB; b++) acc[b] = 0.f;

#pragma unroll 4
    for (int o = 0; o < OSEG; o++) {
        float wv = W[(size_t)(oc * OSEG + o) * HH + h];
#pragma unroll
        for (int b = 0; b < BB; b++)
            acc[b] = fmaf(wv, ls[b * OSEG + o], acc[b]);
    }
#pragma unroll
    for (int b = 0; b < BB; b++)
        g_qpart[(size_t)oc * BB * HH + b * HH + h] = acc[b];
}

// Kernel 2: reduce the OCH query partials -> g_q
__global__ void k_qreduce() {
    const int idx = blockIdx.x * 256 + threadIdx.x;   // b*HH + h
    float s = 0.f;
#pragma unroll
    for (int oc = 0; oc < OCH; oc++)
        s += g_qpart[(size_t)oc * BB * HH + idx];
    g_q[idx] = s;
}

// ---------------------------------------------------------------------
// Kernel 3: fused score + online-softmax + context, single pass over value.
// Block = 512 threads (16 warps), grid (RANGES, BB). Each warp keeps a
// private online-softmax state (m, s, c[1024] as 32 regs/lane); value rows
// are held in registers between the score dot and the context FMA. No
// block syncs in the mainloop. Warps merged via smem tree at block end.
// Lane l, reg 4j+k maps to h = j*128 + l*4 + k.
// ---------------------------------------------------------------------
__global__ __launch_bounds__(512, 1)
void k_fused(const float* __restrict__ value) {
    __shared__ float4 q_sm[HH / 4];          // 4 KB
    __shared__ float4 red_c[(NW / 2) * (HH / 4)]; // 32 KB
    __shared__ float red_m[NW], red_s[NW];

    const int b = blockIdx.y;
    const int r = blockIdx.x;
    const int tid = threadIdx.x;
    const int w = tid >> 5, l = tid & 31;

    const float4* qg = reinterpret_cast<const float4*>(g_q) + b * (HH / 4);
    for (int i = tid; i < HH / 4; i += 512) q_sm[i] = qg[i];
    __syncthreads();

    float cx[32];
#pragma unroll
    for (int i = 0; i < 32; i++) cx[i] = 0.f;
    float mw = -1e30f, sw = 0.f;

    const float4* vb = reinterpret_cast<const float4*>(value)
                     + ((size_t)b * TT + (size_t)r * TR) * (HH / 4);

    for (int it = 0; it < NITER; it++) {
        const int t0 = it * (NW * RPW) + w * RPW;
        const float4* p0 = vb + (size_t)t0 * (HH / 4) + l;
        const float4* p1 = p0 + (HH / 4);

        float4 v0[8], v1[8];
#pragma unroll
        for (int j = 0; j < 8; j++) v0[j] = p0[j * 32];
#pragma unroll
        for (int j = 0; j < 8; j++) v1[j] = p1[j * 32];

        float d0 = 0.f, d1 = 0.f;
#pragma unroll
        for (int j = 0; j < 8; j++) {
            float4 q = q_sm[j * 32 + l];
            d0 = fmaf(v0[j].x, q.x, d0); d0 = fmaf(v0[j].y, q.y, d0);
            d0 = fmaf(v0[j].z, q.z, d0); d0 = fmaf(v0[j].w, q.w, d0);
            d1 = fmaf(v1[j].x, q.x, d1); d1 = fmaf(v1[j].y, q.y, d1);
            d1 = fmaf(v1[j].z, q.z, d1); d1 = fmaf(v1[j].w, q.w, d1);
        }
#pragma unroll
        for (int off = 16; off; off >>= 1) {
            d0 += __shfl_xor_sync(0xFFFFFFFFu, d0, off);
            d1 += __shfl_xor_sync(0xFFFFFFFFu, d1, off);
        }

        const float m_new = fmaxf(mw, fmaxf(d0, d1));
        const float resc = __expf(mw - m_new);
        const float p0s  = __expf(d0 - m_new);
        const float p1s  = __expf(d1 - m_new);
        mw = m_new;
        sw = fmaf(sw, resc, p0s + p1s);
#pragma unroll
        for (int j = 0; j < 8; j++) {
            float t;
            t = cx[4*j+0] * resc; t = fmaf(p0s, v0[j].x, t); cx[4*j+0] = fmaf(p1s, v1[j].x, t);
            t = cx[4*j+1] * resc; t = fmaf(p0s, v0[j].y, t); cx[4*j+1] = fmaf(p1s, v1[j].y, t);
            t = cx[4*j+2] * resc; t = fmaf(p0s, v0[j].z, t); cx[4*j+2] = fmaf(p1s, v1[j].z, t);
            t = cx[4*j+3] * resc; t = fmaf(p0s, v0[j].w, t); cx[4*j+3] = fmaf(p1s, v1[j].w, t);
        }
    }

    // Cross-warp tree merge of (m, s, c) online-softmax partials.
#pragma unroll
    for (int half = NW / 2; half >= 1; half >>= 1) {
        __syncthreads();
        if (w >= half && w < 2 * half) {
            const int slot = w - half;
#pragma unroll
            for (int j = 0; j < 8; j++)
                red_c[slot * (HH / 4) + j * 32 + l] =
                    make_float4(cx[4*j], cx[4*j+1], cx[4*j+2], cx[4*j+3]);
            if (l == 0) { red_m[slot] = mw; red_s[slot] = sw; }
        }
        __syncthreads();
        if (w < half) {
            const float mo = red_m[w], so = red_s[w];
            const float M  = fmaxf(mw, mo);
            const float ea = __expf(mw - M);
            const float eb = __expf(mo - M);
#pragma unroll
            for (int j = 0; j < 8; j++) {
                float4 o = red_c[w * (HH / 4) + j * 32 + l];
                cx[4*j+0] = cx[4*j+0] * ea + o.x * eb;
                cx[4*j+1] = cx[4*j+1] * ea + o.y * eb;
                cx[4*j+2] = cx[4*j+2] * ea + o.z * eb;
                cx[4*j+3] = cx[4*j+3] * ea + o.w * eb;
            }
            sw = sw * ea + so * eb;
            mw = M;
        }
    }

    if (w == 0) {
        float4* cp = reinterpret_cast<float4*>(g_cpart)
                   + (size_t)(b * RANGES + r) * (HH / 4);
#pragma unroll
        for (int j = 0; j < 8; j++)
            cp[j * 32 + l] = make_float4(cx[4*j], cx[4*j+1], cx[4*j+2], cx[4*j+3]);
        if (l == 0) {
            g_mpart[b * RANGES + r] = mw;
            g_spart[b * RANGES + r] = sw;
        }
    }
}

// ---------------------------------------------------------------------
// Kernel 4: combine the RANGES block-partials -> out [B,1,H].
// grid BB, block HH/4 = 256, each thread one float4 of h.
// ---------------------------------------------------------------------
__global__ void k_combine(float* __restrict__ out) {
    const int b = blockIdx.x;
    const int tid = threadIdx.x;

    float M = -1e30f;
#pragma unroll
    for (int rr = 0; rr < RANGES; rr++)
        M = fmaxf(M, g_mpart[b * RANGES + rr]);

    float wgt[RANGES];
    float D = 0.f;
#pragma unroll
    for (int rr = 0; rr < RANGES; rr++) {
        wgt[rr] = __expf(g_mpart[b * RANGES + rr] - M);
        D = fmaf(g_spart[b * RANGES + rr], wgt[rr], D);
    }

    float4 acc = make_float4(0.f, 0.f, 0.f, 0.f);
    const float4* cp = reinterpret_cast<const float4*>(g_cpart)
                     + (size_t)b * RANGES * (HH / 4);
#pragma unroll
    for (int rr = 0; rr < RANGES; rr++) {
        float4 c4 = cp[rr * (HH / 4) + tid];
        acc.x = fmaf(wgt[rr], c4.x, acc.x);
        acc.y = fmaf(wgt[rr], c4.y, acc.y);
        acc.z = fmaf(wgt[rr], c4.z, acc.z);
        acc.w = fmaf(wgt[rr], c4.w, acc.w);
    }
    const float inv = 1.f / D;
    reinterpret_cast<float4*>(out)[b * (HH / 4) + tid] =
        make_float4(acc.x * inv, acc.y * inv, acc.z * inv, acc.w * inv);
}

// ---------------------------------------------------------------------
extern "C" void kernel_launch(void* const* d_in, const int* in_sizes, int n_in,
                              void* d_out, int out_size) {
    const float* value = (const float*)d_in[0];  // [B,T,H]
    const float* last  = (const float*)d_in[1];  // [B,H]
    const float* W     = (const float*)d_in[2];  // [H,H]
    // d_in[3] = bias: constant per-batch shift in scores, cancels in softmax.
    float* out = (float*)d_out;                  // [B,1,H]
    (void)in_sizes; (void)n_in; (void)out_size;

    dim3 gq(HH / 256, OCH);
    k_query_part<<<gq, 256>>>(W, last);

    k_qreduce<<<(BB * HH) / 256, 256>>>();

    dim3 gf(RANGES, BB);
    k_fused<<<gf, 512>>>(value);

    k_combine<<<BB, HH / 4>>>(out);
}

// round 3
// speedup vs baseline: 2.8977x; 1.1546x over previous
#include <cuda_runtime.h>
#include <cstdint>

// Shapes fixed: value [8,4096,1024], last [8,1024], W [1024,1024], b [1024].
#define BB 8
#define TT 4096
#define HH 1024

#define RANGES 16              // T-splits per batch (fused kernel grid.x)
#define TR (TT / RANGES)       // 256 timesteps per block
#define NW 16                  // warps per fused block (512 threads)
#define RPW 2                  // rows per warp per iteration
#define NITER (TR / (NW * RPW))// 8 iterations

#define OCH 32                 // o-splits for query partials
#define OSEG (HH / OCH)        // 32

// -------- scratch (__device__ globals; no allocation allowed) --------
__device__ __align__(16) float g_qpart[OCH * BB * HH]; // 1 MB
__device__ __align__(16) float g_cpart[BB * RANGES * HH];
__device__ float g_mpart[BB * RANGES];
__device__ float g_spart[BB * RANGES];

// ---------------------------------------------------------------------
// Kernel 1: query partials. qpart[oc,b,h] = sum_{o in chunk oc} W[o,h]*last[b,o]
// grid (HH/256, OCH) = 128 blocks, block 256. All 8 batches per W-load;
// W (4 MB) streamed exactly once.
// ---------------------------------------------------------------------
__global__ void k_query_part(const float* __restrict__ W,
                             const float* __restrict__ last) {
    __shared__ float ls[BB * OSEG];
    const int oc = blockIdx.y;
    const int h  = blockIdx.x * 256 + threadIdx.x;

    if (threadIdx.x < BB * OSEG) {
        int b = threadIdx.x / OSEG, o = threadIdx.x % OSEG;
        ls[threadIdx.x] = last[b * HH + oc * OSEG + o];
    }
    __syncthreads();

    float acc[BB];
#pragma unroll
    for (int b = 0; b < BB; b++) acc[b] = 0.f;

#pragma unroll 8
    for (int o = 0; o < OSEG; o++) {
        float wv = W[(size_t)(oc * OSEG + o) * HH + h];
#pragma unroll
        for (int b = 0; b < BB; b++)
            acc[b] = fmaf(wv, ls[b * OSEG + o], acc[b]);
    }
#pragma unroll
    for (int b = 0; b < BB; b++)
        g_qpart[(size_t)oc * BB * HH + b * HH + h] = acc[b];
}

// ---------------------------------------------------------------------
// Kernel 2: fused score + online-softmax + context, single pass over value.
// Block = 512 threads (16 warps), grid (RANGES, BB). Prologue reduces the
// OCH q-partials straight into smem (L2-resident, ~64 KB per block).
// Each warp keeps a private online-softmax state (m, s, c[1024] = 32
// regs/lane); value rows live in registers between the score dot and the
// context FMA. No block syncs in the mainloop.
// Lane l, reg 4j+k maps to h = j*128 + l*4 + k.
// ---------------------------------------------------------------------
__global__ __launch_bounds__(512, 1)
void k_fused(const float* __restrict__ value) {
    __shared__ float4 q_sm[HH / 4];               // 4 KB
    __shared__ float4 red_c[(NW / 2) * (HH / 4)]; // 32 KB
    __shared__ float red_m[NW], red_s[NW];

    const int b = blockIdx.y;
    const int r = blockIdx.x;
    const int tid = threadIdx.x;
    const int w = tid >> 5, l = tid & 31;

    // Prologue: q[b] = sum over OCH partial chunks (replaces k_qreduce).
    if (tid < HH / 4) {
        const float4* qp = reinterpret_cast<const float4*>(g_qpart)
                         + (size_t)b * (HH / 4) + tid;
        float4 s = make_float4(0.f, 0.f, 0.f, 0.f);
#pragma unroll
        for (int oc = 0; oc < OCH; oc++) {
            float4 p = qp[(size_t)oc * BB * (HH / 4)];
            s.x += p.x; s.y += p.y; s.z += p.z; s.w += p.w;
        }
        q_sm[tid] = s;
    }
    __syncthreads();

    float cx[32];
#pragma unroll
    for (int i = 0; i < 32; i++) cx[i] = 0.f;
    float mw = -1e30f, sw = 0.f;

    const float4* vb = reinterpret_cast<const float4*>(value)
                     + ((size_t)b * TT + (size_t)r * TR) * (HH / 4);

    for (int it = 0; it < NITER; it++) {
        const int t0 = it * (NW * RPW) + w * RPW;
        const float4* p0 = vb + (size_t)t0 * (HH / 4) + l;
        const float4* p1 = p0 + (HH / 4);

        float4 v0[8], v1[8];
#pragma unroll
        for (int j = 0; j < 8; j++) v0[j] = p0[j * 32];
#pragma unroll
        for (int j = 0; j < 8; j++) v1[j] = p1[j * 32];

        float d0 = 0.f, d1 = 0.f;
#pragma unroll
        for (int j = 0; j < 8; j++) {
            float4 q = q_sm[j * 32 + l];
            d0 = fmaf(v0[j].x, q.x, d0); d0 = fmaf(v0[j].y, q.y, d0);
            d0 = fmaf(v0[j].z, q.z, d0); d0 = fmaf(v0[j].w, q.w, d0);
            d1 = fmaf(v1[j].x, q.x, d1); d1 = fmaf(v1[j].y, q.y, d1);
            d1 = fmaf(v1[j].z, q.z, d1); d1 = fmaf(v1[j].w, q.w, d1);
        }
#pragma unroll
        for (int off = 16; off; off >>= 1) {
            d0 += __shfl_xor_sync(0xFFFFFFFFu, d0, off);
            d1 += __shfl_xor_sync(0xFFFFFFFFu, d1, off);
        }

        const float m_new = fmaxf(mw, fmaxf(d0, d1));
        const float resc = __expf(mw - m_new);
        const float p0s  = __expf(d0 - m_new);
        const float p1s  = __expf(d1 - m_new);
        mw = m_new;
        sw = fmaf(sw, resc, p0s + p1s);
#pragma unroll
        for (int j = 0; j < 8; j++) {
            float t;
            t = cx[4*j+0] * resc; t = fmaf(p0s, v0[j].x, t); cx[4*j+0] = fmaf(p1s, v1[j].x, t);
            t = cx[4*j+1] * resc; t = fmaf(p0s, v0[j].y, t); cx[4*j+1] = fmaf(p1s, v1[j].y, t);
            t = cx[4*j+2] * resc; t = fmaf(p0s, v0[j].z, t); cx[4*j+2] = fmaf(p1s, v1[j].z, t);
            t = cx[4*j+3] * resc; t = fmaf(p0s, v0[j].w, t); cx[4*j+3] = fmaf(p1s, v1[j].w, t);
        }
    }

    // Cross-warp tree merge of (m, s, c) online-softmax partials.
#pragma unroll
    for (int half = NW / 2; half >= 1; half >>= 1) {
        __syncthreads();
        if (w >= half && w < 2 * half) {
            const int slot = w - half;
#pragma unroll
            for (int j = 0; j < 8; j++)
                red_c[slot * (HH / 4) + j * 32 + l] =
                    make_float4(cx[4*j], cx[4*j+1], cx[4*j+2], cx[4*j+3]);
            if (l == 0) { red_m[slot] = mw; red_s[slot] = sw; }
        }
        __syncthreads();
        if (w < half) {
            const float mo = red_m[w], so = red_s[w];
            const float M  = fmaxf(mw, mo);
            const float ea = __expf(mw - M);
            const float eb = __expf(mo - M);
#pragma unroll
            for (int j = 0; j < 8; j++) {
                float4 o = red_c[w * (HH / 4) + j * 32 + l];
                cx[4*j+0] = cx[4*j+0] * ea + o.x * eb;
                cx[4*j+1] = cx[4*j+1] * ea + o.y * eb;
                cx[4*j+2] = cx[4*j+2] * ea + o.z * eb;
                cx[4*j+3] = cx[4*j+3] * ea + o.w * eb;
            }
            sw = sw * ea + so * eb;
            mw = M;
        }
    }

    if (w == 0) {
        float4* cp = reinterpret_cast<float4*>(g_cpart)
                   + (size_t)(b * RANGES + r) * (HH / 4);
#pragma unroll
        for (int j = 0; j < 8; j++)
            cp[j * 32 + l] = make_float4(cx[4*j], cx[4*j+1], cx[4*j+2], cx[4*j+3]);
        if (l == 0) {
            g_mpart[b * RANGES + r] = mw;
            g_spart[b * RANGES + r] = sw;
        }
    }
}

// ---------------------------------------------------------------------
// Kernel 3: combine the RANGES block-partials -> out [B,1,H].
// grid (BB, 4), block 64; one float4 of h per thread, 16 L2 loads each.
// ---------------------------------------------------------------------
__global__ void k_combine(float* __restrict__ out) {
    const int b = blockIdx.x;
    const int h4 = blockIdx.y * 64 + threadIdx.x;  // float4 index in [0,256)

    float M = -1e30f;
#pragma unroll
    for (int rr = 0; rr < RANGES; rr++)
        M = fmaxf(M, g_mpart[b * RANGES + rr]);

    float wgt[RANGES];
    float D = 0.f;
#pragma unroll
    for (int rr = 0; rr < RANGES; rr++) {
        wgt[rr] = __expf(g_mpart[b * RANGES + rr] - M);
        D = fmaf(g_spart[b * RANGES + rr], wgt[rr], D);
    }

    float4 acc = make_float4(0.f, 0.f, 0.f, 0.f);
    const float4* cp = reinterpret_cast<const float4*>(g_cpart)
                     + (size_t)b * RANGES * (HH / 4);
#pragma unroll
    for (int rr = 0; rr < RANGES; rr++) {
        float4 c4 = cp[rr * (HH / 4) + h4];
        acc.x = fmaf(wgt[rr], c4.x, acc.x);
        acc.y = fmaf(wgt[rr], c4.y, acc.y);
        acc.z = fmaf(wgt[rr], c4.z, acc.z);
        acc.w = fmaf(wgt[rr], c4.w, acc.w);
    }
    const float inv = 1.f / D;
    reinterpret_cast<float4*>(out)[b * (HH / 4) + h4] =
        make_float4(acc.x * inv, acc.y * inv, acc.z * inv, acc.w * inv);
}

// ---------------------------------------------------------------------
extern "C" void kernel_launch(void* const* d_in, const int* in_sizes, int n_in,
                              void* d_out, int out_size) {
    const float* value = (const float*)d_in[0];  // [B,T,H]
    const float* last  = (const float*)d_in[1];  // [B,H]
    const float* W     = (const float*)d_in[2];  // [H,H]
    // d_in[3] = bias: constant per-batch shift in scores, cancels in softmax.
    float* out = (float*)d_out;                  // [B,1,H]
    (void)in_sizes; (void)n_in; (void)out_size;

    dim3 gq(HH / 256, OCH);
    k_query_part<<<gq, 256>>>(W, last);

    dim3 gf(RANGES, BB);
    k_fused<<<gf, 512>>>(value);

    dim3 gc(BB, 4);
    k_combine<<<gc, 64>>>(out);
}

// round 5
// speedup vs baseline: 2.9000x; 1.0008x over previous
#include <cuda_runtime.h>
#include <cstdint>

// Shapes fixed: value [8,4096,1024], last [8,1024], W [1024,1024], b [1024].
#define BB 8
#define TT 4096
#define HH 1024

#define RANGES 32              // T-splits per batch (fused kernel grid.x)
#define TR (TT / RANGES)       // 128 timesteps per block
#define NW 8                   // warps per fused block (256 threads)
#define RPW 2                  // rows per warp per iteration
#define NITER (TR / (NW * RPW))// 8 iterations

#define OCH 64                 // o-splits for query partials
#define OSEG (HH / OCH)        // 16

// -------- scratch (__device__ globals; no allocation allowed) --------
__device__ __align__(16) float g_qpart[OCH * BB * HH]; // 2 MB (L2-resident)
__device__ __align__(16) float g_cpart[BB * RANGES * HH]; // 1 MB
__device__ float g_mpart[BB * RANGES];
__device__ float g_spart[BB * RANGES];

// ---------------------------------------------------------------------
// Kernel 1: query partials. qpart[oc,b,h] = sum_{o in chunk oc} W[o,h]*last[b,o]
// grid (HH/128, OCH) = 512 blocks, block 128. 16 fully-unrolled W loads
// per thread (MLP 16), 8 batches per W element. W (4 MB) streamed once.
// ---------------------------------------------------------------------
__global__ void k_query_part(const float* __restrict__ W,
                             const float* __restrict__ last) {
    __shared__ float ls[BB * OSEG];   // 128 floats
    const int oc = blockIdx.y;
    const int h  = blockIdx.x * 128 + threadIdx.x;

    if (threadIdx.x < BB * OSEG) {
        int b = threadIdx.x / OSEG, o = threadIdx.x % OSEG;
        ls[threadIdx.x] = last[b * HH + oc * OSEG + o];
    }
    __syncthreads();

    float wv[OSEG];
#pragma unroll
    for (int o = 0; o < OSEG; o++)
        wv[o] = W[(size_t)(oc * OSEG + o) * HH + h];

    float acc[BB];
#pragma unroll
    for (int b = 0; b < BB; b++) acc[b] = 0.f;
#pragma unroll
    for (int o = 0; o < OSEG; o++) {
#pragma unroll
        for (int b = 0; b < BB; b++)
            acc[b] = fmaf(wv[o], ls[b * OSEG + o], acc[b]);
    }
#pragma unroll
    for (int b = 0; b < BB; b++)
        g_qpart[(size_t)oc * BB * HH + b * HH + h] = acc[b];
}

// ---------------------------------------------------------------------
// Kernel 2: fused score + online-softmax + context, single pass over value.
// Block = 256 threads (8 warps), grid (RANGES, BB) = 256 blocks -> 2 CTAs
// per SM for latency hiding. Prologue reduces the OCH q-partials from L2
// into smem. Each warp keeps a private online-softmax state (m, s,
// c[1024] = 32 regs/lane); value rows live in registers between the score
// dot and the context FMA. No block syncs in the mainloop.
// Lane l, reg 4j+k maps to h = j*128 + l*4 + k.
// ---------------------------------------------------------------------
__global__ __launch_bounds__(256, 2)
void k_fused(const float* __restrict__ value) {
    __shared__ float4 q_sm[HH / 4];               // 4 KB
    __shared__ float4 red_c[(NW / 2) * (HH / 4)]; // 16 KB
    __shared__ float red_m[NW], red_s[NW];

    const int b = blockIdx.y;
    const int r = blockIdx.x;
    const int tid = threadIdx.x;
    const int w = tid >> 5, l = tid & 31;

    // Prologue: q[b] = sum over OCH partial chunks (L2-resident).
    {
        const float4* qp = reinterpret_cast<const float4*>(g_qpart)
                         + (size_t)b * (HH / 4) + tid;
        float4 s = make_float4(0.f, 0.f, 0.f, 0.f);
#pragma unroll
        for (int oc = 0; oc < OCH; oc++) {
            float4 p = qp[(size_t)oc * BB * (HH / 4)];
            s.x += p.x; s.y += p.y; s.z += p.z; s.w += p.w;
        }
        q_sm[tid] = s;
    }
    __syncthreads();

    float cx[32];
#pragma unroll
    for (int i = 0; i < 32; i++) cx[i] = 0.f;
    float mw = -1e30f, sw = 0.f;

    const float4* vb = reinterpret_cast<const float4*>(value)
                     + ((size_t)b * TT + (size_t)r * TR) * (HH / 4);

    for (int it = 0; it < NITER; it++) {
        const int t0 = it * (NW * RPW) + w * RPW;
        const float4* p0 = vb + (size_t)t0 * (HH / 4) + l;
        const float4* p1 = p0 + (HH / 4);

        float4 v0[8], v1[8];
#pragma unroll
        for (int j = 0; j < 8; j++) v0[j] = p0[j * 32];
#pragma unroll
        for (int j = 0; j < 8; j++) v1[j] = p1[j * 32];

        float d0 = 0.f, d1 = 0.f;
#pragma unroll
        for (int j = 0; j < 8; j++) {
            float4 q = q_sm[j * 32 + l];
            d0 = fmaf(v0[j].x, q.x, d0); d0 = fmaf(v0[j].y, q.y, d0);
            d0 = fmaf(v0[j].z, q.z, d0); d0 = fmaf(v0[j].w, q.w, d0);
            d1 = fmaf(v1[j].x, q.x, d1); d1 = fmaf(v1[j].y, q.y, d1);
            d1 = fmaf(v1[j].z, q.z, d1); d1 = fmaf(v1[j].w, q.w, d1);
        }
#pragma unroll
        for (int off = 16; off; off >>= 1) {
            d0 += __shfl_xor_sync(0xFFFFFFFFu, d0, off);
            d1 += __shfl_xor_sync(0xFFFFFFFFu, d1, off);
        }

        const float m_new = fmaxf(mw, fmaxf(d0, d1));
        const float resc = __expf(mw - m_new);
        const float p0s  = __expf(d0 - m_new);
        const float p1s  = __expf(d1 - m_new);
        mw = m_new;
        sw = fmaf(sw, resc, p0s + p1s);
#pragma unroll
        for (int j = 0; j < 8; j++) {
            float t;
            t = cx[4*j+0] * resc; t = fmaf(p0s, v0[j].x, t); cx[4*j+0] = fmaf(p1s, v1[j].x, t);
            t = cx[4*j+1] * resc; t = fmaf(p0s, v0[j].y, t); cx[4*j+1] = fmaf(p1s, v1[j].y, t);
            t = cx[4*j+2] * resc; t = fmaf(p0s, v0[j].z, t); cx[4*j+2] = fmaf(p1s, v1[j].z, t);
            t = cx[4*j+3] * resc; t = fmaf(p0s, v0[j].w, t); cx[4*j+3] = fmaf(p1s, v1[j].w, t);
        }
    }

    // Cross-warp tree merge of (m, s, c) online-softmax partials.
#pragma unroll
    for (int half = NW / 2; half >= 1; half >>= 1) {
        __syncthreads();
        if (w >= half && w < 2 * half) {
            const int slot = w - half;
#pragma unroll
            for (int j = 0; j < 8; j++)
                red_c[slot * (HH / 4) + j * 32 + l] =
                    make_float4(cx[4*j], cx[4*j+1], cx[4*j+2], cx[4*j+3]);
            if (l == 0) { red_m[slot] = mw; red_s[slot] = sw; }
        }
        __syncthreads();
        if (w < half) {
            const float mo = red_m[w], so = red_s[w];
            const float M  = fmaxf(mw, mo);
            const float ea = __expf(mw - M);
            const float eb = __expf(mo - M);
#pragma unroll
            for (int j = 0; j < 8; j++) {
                float4 o = red_c[w * (HH / 4) + j * 32 + l];
                cx[4*j+0] = cx[4*j+0] * ea + o.x * eb;
                cx[4*j+1] = cx[4*j+1] * ea + o.y * eb;
                cx[4*j+2] = cx[4*j+2] * ea + o.z * eb;
                cx[4*j+3] = cx[4*j+3] * ea + o.w * eb;
            }
            sw = sw * ea + so * eb;
            mw = M;
        }
    }

    if (w == 0) {
        float4* cp = reinterpret_cast<float4*>(g_cpart)
                   + (size_t)(b * RANGES + r) * (HH / 4);
#pragma unroll
        for (int j = 0; j < 8; j++)
            cp[j * 32 + l] = make_float4(cx[4*j], cx[4*j+1], cx[4*j+2], cx[4*j+3]);
        if (l == 0) {
            g_mpart[b * RANGES + r] = mw;
            g_spart[b * RANGES + r] = sw;
        }
    }
}

// ---------------------------------------------------------------------
// Kernel 3: combine the RANGES block-partials -> out [B,1,H].
// grid (BB, 4), block 64; one float4 of h per thread, 32 L2 loads each.
// ---------------------------------------------------------------------
__global__ void k_combine(float* __restrict__ out) {
    const int b = blockIdx.x;
    const int h4 = blockIdx.y * 64 + threadIdx.x;  // float4 index in [0,256)

    float M = -1e30f;
#pragma unroll
    for (int rr = 0; rr < RANGES; rr++)
        M = fmaxf(M, g_mpart[b * RANGES + rr]);

    float D = 0.f;
    float4 acc = make_float4(0.f, 0.f, 0.f, 0.f);
    const float4* cp = reinterpret_cast<const float4*>(g_cpart)
                     + (size_t)b * RANGES * (HH / 4);
#pragma unroll
    for (int rr = 0; rr < RANGES; rr++) {
        const float wgt = __expf(g_mpart[b * RANGES + rr] - M);
        D = fmaf(g_spart[b * RANGES + rr], wgt, D);
        float4 c4 = cp[rr * (HH / 4) + h4];
        acc.x = fmaf(wgt, c4.x, acc.x);
        acc.y = fmaf(wgt, c4.y, acc.y);
        acc.z = fmaf(wgt, c4.z, acc.z);
        acc.w = fmaf(wgt, c4.w, acc.w);
    }
    const float inv = 1.f / D;
    reinterpret_cast<float4*>(out)[b * (HH / 4) + h4] =
        make_float4(acc.x * inv, acc.y * inv, acc.z * inv, acc.w * inv);
}

// ---------------------------------------------------------------------
extern "C" void kernel_launch(void* const* d_in, const int* in_sizes, int n_in,
                              void* d_out, int out_size) {
    const float* value = (const float*)d_in[0];  // [B,T,H]
    const float* last  = (const float*)d_in[1];  // [B,H]
    const float* W     = (const float*)d_in[2];  // [H,H]
    // d_in[3] = bias: constant per-batch shift in scores, cancels in softmax.
    float* out = (float*)d_out;                  // [B,1,H]
    (void)in_sizes; (void)n_in; (void)out_size;

    dim3 gq(HH / 128, OCH);
    k_query_part<<<gq, 128>>>(W, last);

    dim3 gf(RANGES, BB);
    k_fused<<<gf, 256>>>(value);

    dim3 gc(BB, 4);
    k_combine<<<gc, 64>>>(out);
}